// round 11
// baseline (speedup 1.0000x reference)
#include <cuda_runtime.h>
#include <cstdint>

#define BATCH   8192
#define NF      128
#define NH      64
#define SPLIT   3            // 64-row slices per (head, out-half)
#define THREADS 256
#define MAXPH   256
#define XSTRIDE 66           // floats per xT i-row (264B: 8B-aligned, conflict-light)
#define SMEM_W  32768        // W half: 128 x 64 fp32
#define SMEM_X  (NF * XSTRIDE * 4)
#define SMEM_BYTES (SMEM_W + SMEM_X)

typedef unsigned long long ull;

__device__ int g_rows[NH * MAXPH];
__device__ int g_cnt[NH];

__device__ __forceinline__ ull fma2(ull a, ull b, ull c) {
    ull d;
    asm("fma.rn.f32x2 %0, %1, %2, %3;" : "=l"(d) : "l"(a), "l"(b), "l"(c));
    return d;
}
__device__ __forceinline__ float f2lo(ull v) { return __uint_as_float((unsigned int)v); }
__device__ __forceinline__ float f2hi(ull v) { return __uint_as_float((unsigned int)(v >> 32)); }
__device__ __forceinline__ ull dup(float f) {
    ull r;
    asm("mov.b64 %0, {%1, %1};" : "=l"(r) : "f"(f));
    return r;
}

// ---------------------------------------------------------------------------
// Prep (validated in R10): one CTA per head; dtype-detect head_ix, build
// ordered per-head row lists in g_rows/g_cnt.
// ---------------------------------------------------------------------------
__global__ void __launch_bounds__(THREADS) lm_prep(const void* __restrict__ hx) {
    __shared__ int s_wtot[8], s_woff[8], s_n;
    const int tid = threadIdx.x, warp = tid >> 5, lane = tid & 31;
    const int h = blockIdx.x;

    const unsigned* wd = (const unsigned*)hx;
    unsigned a = 0;
    #pragma unroll
    for (int m = 0; m < 8; m++) a |= wd[2 * (tid + m * THREADS) + 1];
    const int is32 = __syncthreads_or(a != 0);

    union { unsigned v[8]; unsigned char b[32]; } u;
    if (is32) {
        const int4* p = (const int4*)hx;
        #pragma unroll
        for (int j = 0; j < 8; j++) {
            int4 q = p[tid * 8 + j];
            u.v[j] = (unsigned)q.x | ((unsigned)q.y << 8) |
                     ((unsigned)q.z << 16) | ((unsigned)q.w << 24);
        }
    } else {
        const ulonglong2* p = (const ulonglong2*)hx;
        #pragma unroll
        for (int j = 0; j < 8; j++) {
            ulonglong2 q0 = p[tid * 16 + 2 * j];
            ulonglong2 q1 = p[tid * 16 + 2 * j + 1];
            u.v[j] = (unsigned)(q0.x & 0xff) | ((unsigned)(q0.y & 0xff) << 8) |
                     ((unsigned)(q1.x & 0xff) << 16) | ((unsigned)(q1.y & 0xff) << 24);
        }
    }

    int cnt = 0;
    #pragma unroll
    for (int j = 0; j < 32; j++) cnt += (u.b[j] == h);
    int pre = cnt;
    #pragma unroll
    for (int off = 1; off < 32; off <<= 1) {
        int t = __shfl_up_sync(~0u, pre, off);
        if (lane >= off) pre += t;
    }
    if (lane == 31) s_wtot[warp] = pre;
    __syncthreads();
    if (tid < 8) {
        int v = s_wtot[tid];
        int ip = v;
        #pragma unroll
        for (int off = 1; off < 8; off <<= 1) {
            int t = __shfl_up_sync(0xffu, ip, off);
            if (tid >= off) ip += t;
        }
        s_woff[tid] = ip - v;
        if (tid == 7) s_n = ip;
    }
    __syncthreads();
    int wr = s_woff[warp] + pre - cnt;
    #pragma unroll
    for (int j = 0; j < 32; j++) {
        if (u.b[j] == h) {
            if (wr < MAXPH) g_rows[h * MAXPH + wr] = tid * 32 + j;
            wr++;
        }
    }
    if (tid == 0) g_cnt[h] = (s_n < MAXPH) ? s_n : MAXPH;
}

// ---------------------------------------------------------------------------
// Main: grid = 64 heads x 2 out-halves x 3 slices = 384 CTAs x 256 thr.
// CTA: 64 rows x 64 outs. Lane owns 2 rows (slots base+2L, base+2L+1) x 8
// outs (warp*8..+7). Inner iter: 1 LDS.64 (x pair) + 2 dup + 2 bcast
// LDS.128 (W) + 8 FMA2 -> fma-pipe-bound. 3 CTAs/SM.
// ---------------------------------------------------------------------------
__global__ void __launch_bounds__(THREADS, 3) lm_main(
    const float* __restrict__ x, const float* __restrict__ wgt,
    const float* __restrict__ bias, float* __restrict__ out)
{
    extern __shared__ unsigned char smem[];
    float* Wsm = reinterpret_cast<float*>(smem);            // [128][64]
    float* xT  = reinterpret_cast<float*>(smem + SMEM_W);   // [128][XSTRIDE]

    const int tid  = threadIdx.x, warp = tid >> 5, lane = tid & 31;
    const int blk  = blockIdx.x;
    const int h    = blk / (2 * SPLIT);
    const int oh   = (blk % (2 * SPLIT)) / SPLIT;
    const int s    = blk % SPLIT;

    const int n = g_cnt[h];
    if (s * 64 >= n) return;          // empty slice: exit before SMEM work

    // --- Stage W half: Wsm[i][j] = wgt[h][i][oh*64+j] (2048 float4) ---
    {
        const float4* src = reinterpret_cast<const float4*>(
            wgt + (size_t)h * NF * NF + oh * 64);
        float4* dst = reinterpret_cast<float4*>(Wsm);
        #pragma unroll
        for (int q = 0; q < 8; q++) {
            int idx = q * THREADS + tid;
            int i = idx >> 4, j4 = idx & 15;
            dst[idx] = src[i * 32 + j4];
        }
    }

    const int* rl = g_rows + h * MAXPH;

    for (int base = s * 64; base < n; base += SPLIT * 64) {
        if (base != s * 64) __syncthreads();   // practically never taken

        // --- Stage 64 x-rows transposed: warp w stages rows w*8..w*8+7.
        //     LDG coalesced (lane -> col); STS stride XSTRIDE (2-way max). ---
        #pragma unroll
        for (int k = 0; k < 8; k++) {
            int slot = base + warp * 8 + k;
            int row  = (slot < n) ? rl[slot] : -1;
            const float* xr = x + (size_t)(row >= 0 ? row : 0) * NF;
            int r = warp * 8 + k;
            #pragma unroll
            for (int j = 0; j < 4; j++) {
                int i = lane + 32 * j;
                xT[i * XSTRIDE + r] = (row >= 0) ? xr[i] : 0.f;
            }
        }
        __syncthreads();

        // --- Compute: 8 independent FMA2 chains ---
        const ull* Wp = reinterpret_cast<const ull*>(Wsm) + warp * 4;
        ull a0 = 0, a1 = 0, a2 = 0, a3 = 0, a4 = 0, a5 = 0, a6 = 0, a7 = 0;
        #pragma unroll 8
        for (int i = 0; i < NF; i++) {
            float2 xv = *reinterpret_cast<const float2*>(xT + i * XSTRIDE + 2 * lane);
            ull x0 = dup(xv.x);
            ull x1 = dup(xv.y);
            const ulonglong2* w2 = reinterpret_cast<const ulonglong2*>(Wp + (size_t)i * 32);
            ulonglong2 wA = w2[0];                 // bcast 16B (outs 0-3 of this warp)
            ulonglong2 wB = w2[1];                 // bcast 16B (outs 4-7)
            a0 = fma2(x0, wA.x, a0);
            a1 = fma2(x0, wA.y, a1);
            a2 = fma2(x0, wB.x, a2);
            a3 = fma2(x0, wB.y, a3);
            a4 = fma2(x1, wA.x, a4);
            a5 = fma2(x1, wA.y, a5);
            a6 = fma2(x1, wB.x, a6);
            a7 = fma2(x1, wB.y, a7);
        }

        // --- Epilogue: +bias, 2 STG.128 per valid row ---
        const float* bp = bias + h * NF + oh * 64 + warp * 8;
        const float4 b0 = *reinterpret_cast<const float4*>(bp);
        const float4 b1 = *reinterpret_cast<const float4*>(bp + 4);
        const int ocol = oh * 64 + warp * 8;

        int slot0 = base + 2 * lane;
        if (slot0 < n) {
            float* op = out + (size_t)rl[slot0] * NF + ocol;
            float4 r0, r1;
            r0.x = f2lo(a0) + b0.x;  r0.y = f2hi(a0) + b0.y;
            r0.z = f2lo(a1) + b0.z;  r0.w = f2hi(a1) + b0.w;
            r1.x = f2lo(a2) + b1.x;  r1.y = f2hi(a2) + b1.y;
            r1.z = f2lo(a3) + b1.z;  r1.w = f2hi(a3) + b1.w;
            *reinterpret_cast<float4*>(op)     = r0;
            *reinterpret_cast<float4*>(op + 4) = r1;
        }
        int slot1 = slot0 + 1;
        if (slot1 < n) {
            float* op = out + (size_t)rl[slot1] * NF + ocol;
            float4 r0, r1;
            r0.x = f2lo(a4) + b0.x;  r0.y = f2hi(a4) + b0.y;
            r0.z = f2lo(a5) + b0.z;  r0.w = f2hi(a5) + b0.w;
            r1.x = f2lo(a6) + b1.x;  r1.y = f2hi(a6) + b1.y;
            r1.z = f2lo(a7) + b1.z;  r1.w = f2hi(a7) + b1.w;
            *reinterpret_cast<float4*>(op)     = r0;
            *reinterpret_cast<float4*>(op + 4) = r1;
        }
    }
}

extern "C" void kernel_launch(void* const* d_in, const int* in_sizes, int n_in,
                              void* d_out, int out_size) {
    const float* x   = (const float*)d_in[0];
    const float* w   = (const float*)d_in[1];
    const float* b   = (const float*)d_in[2];
    const void*  hx  = d_in[3];   // int64 or int32, detected on-device
    float*       out = (float*)d_out;

    cudaFuncSetAttribute(lm_main, cudaFuncAttributeMaxDynamicSharedMemorySize, SMEM_BYTES);

    lm_prep<<<NH, THREADS>>>(hx);
    lm_main<<<NH * 2 * SPLIT, THREADS, SMEM_BYTES>>>(x, w, b, out);
}